// round 3
// baseline (speedup 1.0000x reference)
#include <cuda_runtime.h>
#include <cuda_bf16.h>

// SmoothLDDTLoss: b=2, n=4096.
// Stage 1: tiled O(n^2) pair kernel -> per-block partial (sum, count).
// Stage 2: deterministic fixed-order reduction + final scalar.

#define NPTS   4096
#define NB     2
#define ITILE  256      // i-points per block (= blockDim.x)
#define JTILE  128      // j-points staged in shared per block
#define ITILES (NPTS / ITILE)   // 16
#define JTILES (NPTS / JTILE)   // 32
#define PARTS  (ITILES * JTILES) // 512 partials per batch

__device__ float g_psum[NB][PARTS];
__device__ float g_pcnt[NB][PARTS];

__global__ __launch_bounds__(256) void lddt_pair_kernel(
    const float* __restrict__ pred,
    const float* __restrict__ truec,
    const unsigned char* __restrict__ dna,
    const unsigned char* __restrict__ rna)
{
    __shared__ float4 shA[JTILE];   // pred.x, pred.y, pred.z, nuc_j
    __shared__ float4 shB[JTILE];   // true.x, true.y, true.z, (unused)

    const int b  = blockIdx.z;
    const int i0 = blockIdx.x * ITILE;
    const int j0 = blockIdx.y * JTILE;
    const int t  = threadIdx.x;

    // Cooperative load of the j tile into shared.
    if (t < JTILE) {
        const int j = j0 + t;
        const float* pp = pred  + ((size_t)b * NPTS + j) * 3;
        const float* tp = truec + ((size_t)b * NPTS + j) * 3;
        const float nj = (dna[b * NPTS + j] | rna[b * NPTS + j]) ? 1.0f : 0.0f;
        shA[t] = make_float4(pp[0], pp[1], pp[2], nj);
        shB[t] = make_float4(tp[0], tp[1], tp[2], 0.0f);
    }

    // This thread's i point (registers).
    const int i = i0 + t;
    const float* pp = pred  + ((size_t)b * NPTS + i) * 3;
    const float* tp = truec + ((size_t)b * NPTS + i) * 3;
    const float pxi = pp[0], pyi = pp[1], pzi = pp[2];
    const float txi = tp[0], tyi = tp[1], tzi = tp[2];
    const float ni  = (dna[b * NPTS + i] | rna[b * NPTS + i]) ? 1.0f : 0.0f;

    __syncthreads();

    float sum = 0.0f;
    float cnt = 0.0f;

    // e^{-c} for c in {0.5, 1, 2, 4}
    const float K0 = 0.60653065971f;
    const float K1 = 0.36787944117f;
    const float K2 = 0.13533528324f;
    const float K3 = 0.01831563889f;

    #pragma unroll 4
    for (int jj = 0; jj < JTILE; ++jj) {
        const float4 A = shA[jj];
        const float4 B = shB[jj];

        float dx = pxi - A.x, dy = pyi - A.y, dz = pzi - A.z;
        float pd2 = fmaf(dx, dx, fmaf(dy, dy, dz * dz));
        float ex = txi - B.x, ey = tyi - B.y, ez = tzi - B.z;
        float td2 = fmaf(ex, ex, fmaf(ey, ey, ez * ez));

        pd2 = fmaxf(pd2, 1e-12f);
        td2 = fmaxf(td2, 1e-12f);
        const float pd = pd2 * rsqrtf(pd2);   // sqrt via MUFU.RSQ
        const float td = td2 * rsqrtf(td2);

        const float d = fabsf(td - pd);
        // sigmoid(c - d) = 1 / (1 + e^d * e^{-c}); one exp, four rcp.
        const float E = __expf(d);            // overflow -> inf -> sigmoid 0 (correct limit)
        float eps;
        eps  = __fdividef(1.0f, fmaf(E, K0, 1.0f));
        eps += __fdividef(1.0f, fmaf(E, K1, 1.0f));
        eps += __fdividef(1.0f, fmaf(E, K2, 1.0f));
        eps += __fdividef(1.0f, fmaf(E, K3, 1.0f));

        // cutoff = 30 if both nucleic else 15
        const float cutoff = fmaf(ni * A.w, 15.0f, 15.0f);
        const bool m = (td < cutoff) && (i != (j0 + jj));
        if (m) { sum += eps; cnt += 1.0f; }
    }
    sum *= 0.25f;   // the /4 in eps

    // Block reduction (exact for counts: all integers < 2^24).
    __shared__ float rs[256];
    __shared__ float rc[256];
    rs[t] = sum;
    rc[t] = cnt;
    __syncthreads();
    #pragma unroll
    for (int s = 128; s > 0; s >>= 1) {
        if (t < s) { rs[t] += rs[t + s]; rc[t] += rc[t + s]; }
        __syncthreads();
    }
    if (t == 0) {
        const int p = blockIdx.y * ITILES + blockIdx.x;
        g_psum[b][p] = rs[0];
        g_pcnt[b][p] = rc[0];
    }
}

__global__ __launch_bounds__(256) void lddt_finalize_kernel(float* __restrict__ out)
{
    __shared__ float ssum[256];
    __shared__ float scnt[256];
    __shared__ float lddt_b[NB];
    const int t = threadIdx.x;

    for (int b = 0; b < NB; ++b) {
        float s = 0.0f, c = 0.0f;
        for (int p = t; p < PARTS; p += 256) {
            s += g_psum[b][p];
            c += g_pcnt[b][p];
        }
        ssum[t] = s;
        scnt[t] = c;
        __syncthreads();
        #pragma unroll
        for (int k = 128; k > 0; k >>= 1) {
            if (t < k) { ssum[t] += ssum[t + k]; scnt[t] += scnt[t + k]; }
            __syncthreads();
        }
        if (t == 0) lddt_b[b] = ssum[0] / fmaxf(scnt[0], 1.0f);
        __syncthreads();
    }
    if (t == 0) {
        out[0] = 1.0f - 0.5f * (lddt_b[0] + lddt_b[1]);
    }
}

extern "C" void kernel_launch(void* const* d_in, const int* in_sizes, int n_in,
                              void* d_out, int out_size)
{
    const float*         pred  = (const float*)d_in[0];
    const float*         truec = (const float*)d_in[1];
    const unsigned char* dna   = (const unsigned char*)d_in[2];
    const unsigned char* rna   = (const unsigned char*)d_in[3];

    dim3 grid(ITILES, JTILES, NB);
    lddt_pair_kernel<<<grid, 256>>>(pred, truec, dna, rna);
    lddt_finalize_kernel<<<1, 256>>>((float*)d_out);
}

// round 4
// speedup vs baseline: 1.3791x; 1.3791x over previous
#include <cuda_runtime.h>
#include <cuda_bf16.h>

// SmoothLDDTLoss: b=2, n=4096.
// Symmetry: eps and mask are symmetric in (i,j), diagonal excluded, and
// lddt = sum/count is invariant under restricting to the strict upper
// triangle (both halve). So we compute i<j only.
// Stage 1: tiled upper-triangle pair kernel -> per-block partial (sum, count).
// Stage 2: deterministic fixed-order reduction + final scalar.

#define NPTS   4096
#define NB     2
#define ITILE  256      // i-points per block (= blockDim.x)
#define JTILE  128      // j-points staged in shared per block
#define ITILES (NPTS / ITILE)   // 16
#define JTILES (NPTS / JTILE)   // 32
#define PARTS  (ITILES * JTILES) // 512 partial slots per batch (some stay 0)

__device__ float g_psum[NB][PARTS];   // zero-initialized at module load;
__device__ float g_pcnt[NB][PARTS];   // skipped (lower-triangle) slots stay 0.

__global__ __launch_bounds__(256) void lddt_pair_kernel(
    const float* __restrict__ pred,
    const float* __restrict__ truec,
    const unsigned char* __restrict__ dna,
    const unsigned char* __restrict__ rna)
{
    const int ti = blockIdx.x;
    const int tj = blockIdx.y;
    const int b  = blockIdx.z;

    // Strict upper triangle only: tile needs some j > i, i.e. tj*128+127 > ti*256.
    if ((tj + 1) * JTILE <= ti * ITILE) return;

    __shared__ float4 shA[JTILE];   // pred.x, pred.y, pred.z, nuc_j
    __shared__ float4 shB[JTILE];   // true.x, true.y, true.z, (unused)

    const int i0 = ti * ITILE;
    const int j0 = tj * JTILE;
    const int t  = threadIdx.x;

    if (t < JTILE) {
        const int j = j0 + t;
        const float* pp = pred  + ((size_t)b * NPTS + j) * 3;
        const float* tp = truec + ((size_t)b * NPTS + j) * 3;
        const float nj = (dna[b * NPTS + j] | rna[b * NPTS + j]) ? 1.0f : 0.0f;
        shA[t] = make_float4(pp[0], pp[1], pp[2], nj);
        shB[t] = make_float4(tp[0], tp[1], tp[2], 0.0f);
    }

    const int i = i0 + t;
    const float* pp = pred  + ((size_t)b * NPTS + i) * 3;
    const float* tp = truec + ((size_t)b * NPTS + i) * 3;
    const float pxi = pp[0], pyi = pp[1], pzi = pp[2];
    const float txi = tp[0], tyi = tp[1], tzi = tp[2];
    const float ni15 = (dna[b * NPTS + i] | rna[b * NPTS + i]) ? 15.0f : 0.0f;

    __syncthreads();

    float sum = 0.0f;
    float cnt = 0.0f;

    // e^{-c} for c in {0.5, 1, 2, 4}
    const float K0 = 0.60653065971f;
    const float K1 = 0.36787944117f;
    const float K2 = 0.13533528324f;
    const float K3 = 0.01831563889f;

    #pragma unroll 4
    for (int jj = 0; jj < JTILE; ++jj) {
        const float4 A = shA[jj];
        const float4 B = shB[jj];

        float dx = pxi - A.x, dy = pyi - A.y, dz = pzi - A.z;
        float pd2 = fmaf(dx, dx, fmaf(dy, dy, dz * dz));
        float ex = txi - B.x, ey = tyi - B.y, ez = tzi - B.z;
        float td2 = fmaf(ex, ex, fmaf(ey, ey, ez * ez));

        pd2 = fmaxf(pd2, 1e-12f);
        td2 = fmaxf(td2, 1e-12f);
        const float pd = pd2 * rsqrtf(pd2);   // sqrt via MUFU.RSQ
        const float td = td2 * rsqrtf(td2);

        // d clamped at 20: sigmoid tail < 3e-9 there, and keeps E^4 finite.
        const float d = fminf(fabsf(td - pd), 20.0f);
        const float E = __expf(d);            // sigmoid(c-d) = 1/(1 + E*e^{-c})

        // Sum of four reciprocals over a common denominator: ONE division.
        const float p1 = fmaf(E, K0, 1.0f);
        const float p2 = fmaf(E, K1, 1.0f);
        const float p3 = fmaf(E, K2, 1.0f);
        const float p4 = fmaf(E, K3, 1.0f);
        const float q12 = p1 * p2;
        const float q34 = p3 * p4;
        const float num = fmaf(q34, p1 + p2, q12 * (p3 + p4));
        const float eps = __fdividef(num, q12 * q34);

        // cutoff = 30 if both nucleic else 15
        const float cutoff = fmaf(ni15, A.w, 15.0f);
        const bool m = (td < cutoff) && ((j0 + jj) > i);
        if (m) { sum += eps; cnt += 1.0f; }
    }
    sum *= 0.25f;   // the /4 in eps

    // Block reduction (counts exact: integers < 2^24).
    __shared__ float rs[256];
    __shared__ float rc[256];
    rs[t] = sum;
    rc[t] = cnt;
    __syncthreads();
    #pragma unroll
    for (int s = 128; s > 0; s >>= 1) {
        if (t < s) { rs[t] += rs[t + s]; rc[t] += rc[t + s]; }
        __syncthreads();
    }
    if (t == 0) {
        const int p = tj * ITILES + ti;
        g_psum[b][p] = rs[0];
        g_pcnt[b][p] = rc[0];
    }
}

__global__ __launch_bounds__(512) void lddt_finalize_kernel(float* __restrict__ out)
{
    __shared__ float ss[512];
    __shared__ float sc[512];
    const int t = threadIdx.x;      // 0..511
    const int b = t >> 8;           // batch handled by this half
    const int l = t & 255;

    float s = 0.0f, c = 0.0f;
    #pragma unroll
    for (int p = l; p < PARTS; p += 256) {
        s += g_psum[b][p];
        c += g_pcnt[b][p];
    }
    ss[t] = s;
    sc[t] = c;
    __syncthreads();
    #pragma unroll
    for (int k = 128; k > 0; k >>= 1) {
        if (l < k) { ss[t] += ss[t + k]; sc[t] += sc[t + k]; }
        __syncthreads();
    }
    if (t == 0) {
        const float l0 = ss[0]   / fmaxf(sc[0],   1.0f);
        const float l1 = ss[256] / fmaxf(sc[256], 1.0f);
        out[0] = 1.0f - 0.5f * (l0 + l1);
    }
}

extern "C" void kernel_launch(void* const* d_in, const int* in_sizes, int n_in,
                              void* d_out, int out_size)
{
    const float*         pred  = (const float*)d_in[0];
    const float*         truec = (const float*)d_in[1];
    const unsigned char* dna   = (const unsigned char*)d_in[2];
    const unsigned char* rna   = (const unsigned char*)d_in[3];

    dim3 grid(ITILES, JTILES, NB);
    lddt_pair_kernel<<<grid, 256>>>(pred, truec, dna, rna);
    lddt_finalize_kernel<<<1, 512>>>((float*)d_out);
}

// round 5
// speedup vs baseline: 1.9796x; 1.4354x over previous
#include <cuda_runtime.h>

// SmoothLDDTLoss, b=2, n=4096. Upper-triangle only (lddt ratio invariant).
// Single fused kernel: triangle pair tiles -> per-block partials -> last
// block (ticket) reduces deterministically and writes the scalar loss.
//
// Math: all coords pre-scaled by log2(e); then d_scaled = |td-pd| feeds
// ex2 directly and the cutoff compare uses scaled cutoffs.
// sum of 4 sigmoids = num(E)/den(E), E = 2^d_scaled, rational expansion of
// sum_k 1/(1+E*e^{-c_k}), c = {0.5,1,2,4}.

#define NPTS   4096
#define NB     2
#define ITILE  256
#define JTILE  64
#define NTILES 544                 // sum_{ti=0..15} (64 - 4*ti)
#define TOTAL_BLKS (NTILES * NB)

typedef unsigned long long ull;

__device__ float g_psum[NB][NTILES];
__device__ float g_pcnt[NB][NTILES];
__device__ unsigned int g_ticket = 0;

__device__ __forceinline__ ull pk2(float lo, float hi) {
    ull r; asm("mov.b64 %0,{%1,%2};" : "=l"(r) : "f"(lo), "f"(hi)); return r;
}
__device__ __forceinline__ void upk2(float& lo, float& hi, ull v) {
    asm("mov.b64 {%0,%1},%2;" : "=f"(lo), "=f"(hi) : "l"(v));
}
__device__ __forceinline__ ull fma2(ull a, ull b, ull c) {
    ull d; asm("fma.rn.f32x2 %0,%1,%2,%3;" : "=l"(d) : "l"(a), "l"(b), "l"(c)); return d;
}
__device__ __forceinline__ ull add2(ull a, ull b) {
    ull d; asm("add.rn.f32x2 %0,%1,%2;" : "=l"(d) : "l"(a), "l"(b)); return d;
}
__device__ __forceinline__ float rsqrt_a(float x) {
    float r; asm("rsqrt.approx.f32 %0,%1;" : "=f"(r) : "f"(x)); return r;
}
__device__ __forceinline__ float ex2_a(float x) {
    float r; asm("ex2.approx.f32 %0,%1;" : "=f"(r) : "f"(x)); return r;
}
__device__ __forceinline__ float rcp_a(float x) {
    float r; asm("rcp.approx.f32 %0,%1;" : "=f"(r) : "f"(x)); return r;
}

// Scaled-domain constants (everything multiplied by log2(e) = 1.4426950409)
#define F_L2E   1.4426950408889634f
#define F_C15L  21.640425613f        // 15 * log2e
#define F_CLAMP 28.853900818f        // 20 * log2e (sigmoid tail < 3e-9 there)
#define F_EPS2  2.0813690e-12f       // 1e-12 * log2e^2 (folded sqrt clip)

template<bool DIAG>
__device__ __forceinline__ void pair_loop(
    const ulonglong2* __restrict__ shPA, const ulonglong2* __restrict__ shPB,
    const ulonglong2* __restrict__ shTA, const ull* __restrict__ shTZ,
    ull pxi2, ull pyi2, ull pzi2, ull txi2, ull tyi2, ull tzi2,
    float nif, int i, int j0, float& sum, float& cnt)
{
    const ull EPS2P = pk2(F_EPS2, F_EPS2);
    const float cN0 = 4.0f, cN2 = 0.75065586f;
    const float cD0 = 1.0f, cD2 = 0.37532793f;

    #pragma unroll 2
    for (int p = 0; p < JTILE / 2; ++p) {
        const ulonglong2 PA = shPA[p];
        const ulonglong2 PB = shPB[p];
        const ulonglong2 TA = shTA[p];
        const ull        TZ = shTZ[p];

        // packed squared distances, eps folded in (j coords stored negated)
        ull dx = add2(pxi2, PA.x), dy = add2(pyi2, PA.y), dz = add2(pzi2, PB.x);
        ull pq = fma2(dx, dx, EPS2P); pq = fma2(dy, dy, pq); pq = fma2(dz, dz, pq);
        ull ex = add2(txi2, TA.x), ey = add2(tyi2, TA.y), ez = add2(tzi2, TZ);
        ull tq = fma2(ex, ex, EPS2P); tq = fma2(ey, ey, tq); tq = fma2(ez, ez, tq);

        float pq0, pq1, tq0, tq1;
        upk2(pq0, pq1, pq); upk2(tq0, tq1, tq);

        const float pd0 = pq0 * rsqrt_a(pq0);
        const float pd1 = pq1 * rsqrt_a(pq1);
        const float td0 = tq0 * rsqrt_a(tq0);
        const float td1 = tq1 * rsqrt_a(tq1);

        const float m0 = fminf(fabsf(td0 - pd0), F_CLAMP);
        const float m1 = fminf(fabsf(td1 - pd1), F_CLAMP);
        const float E0 = ex2_a(m0);
        const float E1 = ex2_a(m1);

        // sum_k sigmoid(ck - d) = num(E)/den(E); coeffs are elementary
        // symmetric sums of e^{-c_k}. Immediate-form FFMA multipliers.
        const float E0s = E0 * E0;
        const float E1s = E1 * E1;
        float na0 = fmaf(E0, 3.3841831f, cN0);
        float nb0 = fmaf(E0, 0.03669948f, cN2);
        const float num0 = fmaf(nb0, E0s, na0);
        float da0 = fmaf(E0, 1.1280610f, cD0);
        float db0 = fmaf(E0, 0.03669948f, cD2);
        float dc0 = fmaf(db0, E0s, da0);
        const float E0q = E0s * E0s;
        const float den0 = fmaf(E0q, 5.5308442e-4f, dc0);

        float na1 = fmaf(E1, 3.3841831f, cN0);
        float nb1 = fmaf(E1, 0.03669948f, cN2);
        const float num1 = fmaf(nb1, E1s, na1);
        float da1 = fmaf(E1, 1.1280610f, cD0);
        float db1 = fmaf(E1, 0.03669948f, cD2);
        float dc1 = fmaf(db1, E1s, da1);
        const float E1q = E1s * E1s;
        const float den1 = fmaf(E1q, 5.5308442e-4f, dc1);

        float nj0, nj1; upk2(nj0, nj1, PB.y);
        const float cs0 = fmaf(nj0, nif, F_C15L);   // 15 or 30, scaled
        const float cs1 = fmaf(nj1, nif, F_C15L);
        const float r0 = rcp_a(den0);
        const float r1 = rcp_a(den1);

        bool ok0 = td0 < cs0;
        bool ok1 = td1 < cs1;
        if (DIAG) {
            const int j = j0 + 2 * p;
            ok0 = ok0 && (j > i);
            ok1 = ok1 && (j + 1 > i);
        }
        if (ok0) { sum = fmaf(num0, r0, sum); cnt += 1.0f; }
        if (ok1) { sum = fmaf(num1, r1, sum); cnt += 1.0f; }
    }
}

__global__ __launch_bounds__(256, 4) void lddt_fused_kernel(
    const float* __restrict__ pred,
    const float* __restrict__ truec,
    const unsigned char* __restrict__ dna,
    const unsigned char* __restrict__ rna,
    float* __restrict__ out)
{
    __shared__ ulonglong2 shPA[JTILE / 2];  // (-px pair),(-py pair)  [scaled]
    __shared__ ulonglong2 shPB[JTILE / 2];  // (-pz pair),(nj pair)
    __shared__ ulonglong2 shTA[JTILE / 2];  // (-tx pair),(-ty pair)
    __shared__ ull        shTZ[JTILE / 2];  // (-tz pair)
    __shared__ float red[256], redc[256];
    __shared__ float lddt_sh[NB];
    __shared__ unsigned int amLast;

    const int b    = blockIdx.y;
    const int tlin = blockIdx.x;
    const int t    = threadIdx.x;

    // Decode linear tile id -> (ti, tj); cum(ti) = 2*ti*(33-ti); exact at
    // boundaries (disc is a perfect square there).
    int ti = (int)((33.0f - sqrtf((float)(1089 - 2 * tlin))) * 0.5f);
    if (ti > 15) ti = 15;
    if (ti < 0)  ti = 0;
    while (ti > 0 && 2 * ti * (33 - ti) > tlin) --ti;
    while (2 * (ti + 1) * (32 - ti) <= tlin) ++ti;
    const int tj = 4 * ti + (tlin - 2 * ti * (33 - ti));

    const int i0 = ti * ITILE;
    const int j0 = tj * JTILE;

    // Stage the j tile (scaled by log2e, coords negated for add-based sub).
    if (t < JTILE) {
        const int j = j0 + t;
        const float* pp = pred  + ((size_t)b * NPTS + j) * 3;
        const float* tp = truec + ((size_t)b * NPTS + j) * 3;
        const int p = t >> 1, lane = t & 1;
        float* fPA = (float*)shPA; float* fPB = (float*)shPB;
        float* fTA = (float*)shTA; float* fTZ = (float*)shTZ;
        fPA[4 * p + lane]     = -pp[0] * F_L2E;
        fPA[4 * p + 2 + lane] = -pp[1] * F_L2E;
        fPB[4 * p + lane]     = -pp[2] * F_L2E;
        fPB[4 * p + 2 + lane] = (dna[b * NPTS + j] | rna[b * NPTS + j]) ? 1.0f : 0.0f;
        fTA[4 * p + lane]     = -tp[0] * F_L2E;
        fTA[4 * p + 2 + lane] = -tp[1] * F_L2E;
        fTZ[2 * p + lane]     = -tp[2] * F_L2E;
    }

    // This thread's i point (scaled), duplicated into packed lanes.
    const int i = i0 + t;
    const float* pp = pred  + ((size_t)b * NPTS + i) * 3;
    const float* tp = truec + ((size_t)b * NPTS + i) * 3;
    const float pxi = pp[0] * F_L2E, pyi = pp[1] * F_L2E, pzi = pp[2] * F_L2E;
    const float txi = tp[0] * F_L2E, tyi = tp[1] * F_L2E, tzi = tp[2] * F_L2E;
    const float nif = (dna[b * NPTS + i] | rna[b * NPTS + i]) ? F_C15L : 0.0f;
    const ull pxi2 = pk2(pxi, pxi), pyi2 = pk2(pyi, pyi), pzi2 = pk2(pzi, pzi);
    const ull txi2 = pk2(txi, txi), tyi2 = pk2(tyi, tyi), tzi2 = pk2(tzi, tzi);

    __syncthreads();

    float sum = 0.0f, cnt = 0.0f;
    if (tj >= 4 * ti + 4) {
        pair_loop<false>(shPA, shPB, shTA, shTZ, pxi2, pyi2, pzi2,
                         txi2, tyi2, tzi2, nif, i, j0, sum, cnt);
    } else {
        pair_loop<true>(shPA, shPB, shTA, shTZ, pxi2, pyi2, pzi2,
                        txi2, tyi2, tzi2, nif, i, j0, sum, cnt);
    }

    // Block reduction (counts exact: integers < 2^24).
    red[t] = sum; redc[t] = cnt;
    __syncthreads();
    #pragma unroll
    for (int s = 128; s > 0; s >>= 1) {
        if (t < s) { red[t] += red[t + s]; redc[t] += redc[t + s]; }
        __syncthreads();
    }

    if (t == 0) {
        g_psum[b][tlin] = red[0];
        g_pcnt[b][tlin] = redc[0];
        __threadfence();
        const unsigned int old = atomicAdd(&g_ticket, 1u);
        amLast = (old == TOTAL_BLKS - 1) ? 1u : 0u;
    }
    __syncthreads();

    if (amLast) {
        // Deterministic fixed-order final reduction over all partials.
        for (int bb = 0; bb < NB; ++bb) {
            float s = 0.0f, c = 0.0f;
            for (int p = t; p < NTILES; p += 256) {
                s += g_psum[bb][p];
                c += g_pcnt[bb][p];
            }
            red[t] = s; redc[t] = c;
            __syncthreads();
            #pragma unroll
            for (int k = 128; k > 0; k >>= 1) {
                if (t < k) { red[t] += red[t + k]; redc[t] += redc[t + k]; }
                __syncthreads();
            }
            if (t == 0) lddt_sh[bb] = 0.25f * red[0] / fmaxf(redc[0], 1.0f);
            __syncthreads();
        }
        if (t == 0) {
            out[0] = 1.0f - 0.5f * (lddt_sh[0] + lddt_sh[1]);
            g_ticket = 0;   // reset for next (graph-replayed) call
        }
    }
}

extern "C" void kernel_launch(void* const* d_in, const int* in_sizes, int n_in,
                              void* d_out, int out_size)
{
    const float*         pred  = (const float*)d_in[0];
    const float*         truec = (const float*)d_in[1];
    const unsigned char* dna   = (const unsigned char*)d_in[2];
    const unsigned char* rna   = (const unsigned char*)d_in[3];

    dim3 grid(NTILES, NB);
    lddt_fused_kernel<<<grid, 256>>>(pred, truec, dna, rna, (float*)d_out);
}

// round 8
// speedup vs baseline: 2.1106x; 1.0662x over previous
#include <cuda_runtime.h>

// SmoothLDDTLoss, b=2, n=4096. Upper-triangle only (lddt = sum/count is
// invariant under halving both). Single fused kernel:
//   - per-block 512-segment piecewise-linear LUT for
//     eps(d) = 0.25 * sum_k sigmoid(c_k - d), c = {0.5,1,2,4}
//   - triangle pair tiles -> per-block partials
//   - last block (ticket) reduces in fixed order, writes scalar loss.

#define NPTS   4096
#define NB     2
#define ITILE  256
#define JTILE  64
#define NTILES 544                 // sum_{ti=0..15} (64 - 4*ti)
#define TOTAL_BLKS (NTILES * NB)

#define NSEG   512
#define SEG_SCALE 32.0f            // segments of width 1/32 over d in [0,16]

__device__ float g_psum[NB][NTILES];
__device__ float g_pcnt[NB][NTILES];
__device__ unsigned int g_ticket = 0;

__device__ __forceinline__ float sigf(float z) {
    return 1.0f / (1.0f + __expf(-z));
}
__device__ __forceinline__ float eps_exact(float d) {
    return 0.25f * (sigf(0.5f - d) + sigf(1.0f - d) +
                    sigf(2.0f - d) + sigf(4.0f - d));
}

template<bool DIAG>
__device__ __forceinline__ void pair_loop(
    const float4* __restrict__ shP, const float4* __restrict__ shT,
    const float2* __restrict__ lut,
    float pxi, float pyi, float pzi,
    float txi, float tyi, float tzi,
    float ni15, int i, int j0, float& sum, float& cnt)
{
    #pragma unroll 4
    for (int jj = 0; jj < JTILE; ++jj) {
        const float4 P = shP[jj];   // px, py, pz, nj(0/1)
        const float4 T = shT[jj];   // tx, ty, tz, -

        const float dx = pxi - P.x, dy = pyi - P.y, dz = pzi - P.z;
        const float pd2 = fmaf(dx, dx, fmaf(dy, dy, fmaf(dz, dz, 1e-12f)));
        const float ex = txi - T.x, ey = tyi - T.y, ez = tzi - T.z;
        const float td2 = fmaf(ex, ex, fmaf(ey, ey, fmaf(ez, ez, 1e-12f)));

        const float pd = pd2 * rsqrtf(pd2);
        const float td = td2 * rsqrtf(td2);
        const float d  = fabsf(td - pd);

        int idx = __float2int_rz(d * SEG_SCALE);
        idx = min(idx, NSEG - 1);
        const float2 ab = lut[idx];
        const float eps = fmaf(ab.y, d, ab.x);

        const float cs = fmaf(P.w, ni15, 15.0f);   // 15 or 30
        bool ok = td < cs;
        if (DIAG) ok = ok && ((j0 + jj) > i);
        if (ok) { sum += eps; cnt += 1.0f; }
    }
}

__global__ __launch_bounds__(256) void lddt_fused_kernel(
    const float* __restrict__ pred,
    const float* __restrict__ truec,
    const unsigned char* __restrict__ dna,
    const unsigned char* __restrict__ rna,
    float* __restrict__ out)
{
    __shared__ float2 lut[NSEG];       // 4 KB
    __shared__ float4 shP[JTILE];      // 1 KB
    __shared__ float4 shT[JTILE];      // 1 KB
    __shared__ float red[256], redc[256];
    __shared__ float lddt_sh[NB];
    __shared__ unsigned int amLast;

    const int b    = blockIdx.y;
    const int tlin = blockIdx.x;
    const int t    = threadIdx.x;

    // Build the eps LUT: segment k covers [k/32, (k+1)/32); eps ~= a + b*d.
    for (int k = t; k < NSEG; k += 256) {
        const float x0 = (float)k * (1.0f / SEG_SCALE);
        const float x1 = x0 + (1.0f / SEG_SCALE);
        const float f0 = eps_exact(x0);
        const float bslope = (k == NSEG - 1) ? 0.0f
                             : (eps_exact(x1) - f0) * SEG_SCALE;
        lut[k] = make_float2(fmaf(-bslope, x0, f0), bslope);
    }

    // Decode linear tile id -> (ti, tj); cum(ti) = 2*ti*(33-ti).
    int ti = (int)((33.0f - sqrtf((float)(1089 - 2 * tlin))) * 0.5f);
    if (ti > 15) ti = 15;
    if (ti < 0)  ti = 0;
    while (ti > 0 && 2 * ti * (33 - ti) > tlin) --ti;
    while (2 * (ti + 1) * (32 - ti) <= tlin) ++ti;
    const int tj = 4 * ti + (tlin - 2 * ti * (33 - ti));

    const int i0 = ti * ITILE;
    const int j0 = tj * JTILE;

    // Stage the j tile.
    if (t < JTILE) {
        const int j = j0 + t;
        const float* pp = pred  + ((size_t)b * NPTS + j) * 3;
        const float* tp = truec + ((size_t)b * NPTS + j) * 3;
        const float nj = (dna[b * NPTS + j] | rna[b * NPTS + j]) ? 1.0f : 0.0f;
        shP[t] = make_float4(pp[0], pp[1], pp[2], nj);
        shT[t] = make_float4(tp[0], tp[1], tp[2], 0.0f);
    }

    // This thread's i point.
    const int i = i0 + t;
    const float* pp = pred  + ((size_t)b * NPTS + i) * 3;
    const float* tp = truec + ((size_t)b * NPTS + i) * 3;
    const float pxi = pp[0], pyi = pp[1], pzi = pp[2];
    const float txi = tp[0], tyi = tp[1], tzi = tp[2];
    const float ni15 = (dna[b * NPTS + i] | rna[b * NPTS + i]) ? 15.0f : 0.0f;

    __syncthreads();

    float sum = 0.0f, cnt = 0.0f;
    if (tj >= 4 * ti + 4) {
        pair_loop<false>(shP, shT, lut, pxi, pyi, pzi, txi, tyi, tzi,
                         ni15, i, j0, sum, cnt);
    } else {
        pair_loop<true>(shP, shT, lut, pxi, pyi, pzi, txi, tyi, tzi,
                        ni15, i, j0, sum, cnt);
    }

    // Block reduction (counts exact: integers < 2^24).
    red[t] = sum; redc[t] = cnt;
    __syncthreads();
    #pragma unroll
    for (int s = 128; s > 0; s >>= 1) {
        if (t < s) { red[t] += red[t + s]; redc[t] += redc[t + s]; }
        __syncthreads();
    }

    if (t == 0) {
        g_psum[b][tlin] = red[0];
        g_pcnt[b][tlin] = redc[0];
        __threadfence();
        const unsigned int old = atomicAdd(&g_ticket, 1u);
        amLast = (old == TOTAL_BLKS - 1) ? 1u : 0u;
    }
    __syncthreads();

    if (amLast) {
        // Deterministic fixed-order final reduction over all partials.
        for (int bb = 0; bb < NB; ++bb) {
            float s = 0.0f, c = 0.0f;
            for (int p = t; p < NTILES; p += 256) {
                s += g_psum[bb][p];
                c += g_pcnt[bb][p];
            }
            red[t] = s; redc[t] = c;
            __syncthreads();
            #pragma unroll
            for (int k = 128; k > 0; k >>= 1) {
                if (t < k) { red[t] += red[t + k]; redc[t] += redc[t + k]; }
                __syncthreads();
            }
            if (t == 0) lddt_sh[bb] = red[0] / fmaxf(redc[0], 1.0f);
            __syncthreads();
        }
        if (t == 0) {
            out[0] = 1.0f - 0.5f * (lddt_sh[0] + lddt_sh[1]);
            g_ticket = 0;   // reset for next graph replay
        }
    }
}

extern "C" void kernel_launch(void* const* d_in, const int* in_sizes, int n_in,
                              void* d_out, int out_size)
{
    const float*         pred  = (const float*)d_in[0];
    const float*         truec = (const float*)d_in[1];
    const unsigned char* dna   = (const unsigned char*)d_in[2];
    const unsigned char* rna   = (const unsigned char*)d_in[3];

    dim3 grid(NTILES, NB);
    lddt_fused_kernel<<<grid, 256>>>(pred, truec, dna, rna, (float*)d_out);
}